// round 14
// baseline (speedup 1.0000x reference)
#include <cuda_runtime.h>
#include <cstddef>

// SegmentedPolynomialProductJit: out[e,k,u] = sum_{paths (i,j,k,c)} c * a[idx_a[e], i, u] * b[e, j, u]
// scatter-added into out[idx_out[e]].
// SA=4, SB=3, SC=4, U=32, paths: all (i,j), k=(i+j)%4, c=0.1*(i+1)+0.01*(j+1).
//
// Evidence log:
// R4:  baseline 150.9us, 1.0 GB HBM (83.6% SOL) vs ~590 MB floor -> b-stream L2 thrash.
// R8:  __ldcs on b -> 129.0us, 775 MB. WIN.
// R12: 4thr/edge + v8 evict hints -> 175us, traffic unchanged, occ 30.8%. FAILED:
//      evict_last pinning ineffective; occupancy is the latency-hiding lever.
// R13: 128-thr blocks -> 126.0us, occ 53.5%, DRAM 77.6%. Small WIN.
//      Trend: DRAM% ~ linear in occupancy at fixed 775 MB traffic.
// R14: force 40 regs via __launch_bounds__(128, 12) -> 1536 thr/SM cap (75%).

#define SA 4
#define SB 3
#define SC 4
#define UE 32
#define A_ROW (SA * UE)   // 128 floats
#define B_ROW (SB * UE)   // 96 floats
#define O_ROW (SC * UE)   // 128 floats

// 8 threads per edge; each thread owns one float4 (4 consecutive u) across all segments.
__global__ __launch_bounds__(128, 12) void spp_kernel(
    const float* __restrict__ a,
    const float* __restrict__ b,
    const int*   __restrict__ idx_a,
    const int*   __restrict__ idx_out,
    float*       __restrict__ out,
    int E)
{
    long long tid = (long long)blockIdx.x * blockDim.x + threadIdx.x;
    int e = (int)(tid >> 3);
    if (e >= E) return;
    int q = (int)(tid & 7);          // float4 index within a U=32 segment (8 quads)

    const int ia = __ldg(idx_a + e);
    const int io = __ldg(idx_out + e);

    const float4* arow = reinterpret_cast<const float4*>(a) + (size_t)ia * (A_ROW / 4) + q;
    const float4* brow = reinterpret_cast<const float4*>(b) + (size_t)e  * (B_ROW / 4) + q;

    float4 A[SA], B[SB];
#pragma unroll
    for (int i = 0; i < SA; i++) A[i] = __ldg(arow + i * (UE / 4));      // reused: keep cached
#pragma unroll
    for (int j = 0; j < SB; j++) B[j] = __ldcs(brow + j * (UE / 4));     // read-once: streaming

    float4 O[SC];
#pragma unroll
    for (int k = 0; k < SC; k++) { O[k].x = 0.f; O[k].y = 0.f; O[k].z = 0.f; O[k].w = 0.f; }

#pragma unroll
    for (int i = 0; i < SA; i++) {
#pragma unroll
        for (int j = 0; j < SB; j++) {
            const int k = (i + j) & 3;
            const float c = 0.1f * (float)(i + 1) + 0.01f * (float)(j + 1);
            // pre-scale a by the path coefficient, then one fma per component
            float cax = c * A[i].x;
            float cay = c * A[i].y;
            float caz = c * A[i].z;
            float caw = c * A[i].w;
            O[k].x = fmaf(cax, B[j].x, O[k].x);
            O[k].y = fmaf(cay, B[j].y, O[k].y);
            O[k].z = fmaf(caz, B[j].z, O[k].z);
            O[k].w = fmaf(caw, B[j].w, O[k].w);
        }
    }

    float* orow = out + (size_t)io * O_ROW + q * 4;
#pragma unroll
    for (int k = 0; k < SC; k++) {
        float* p = orow + k * UE;
        asm volatile("red.global.add.v4.f32 [%0], {%1, %2, %3, %4};"
                     :: "l"(p), "f"(O[k].x), "f"(O[k].y), "f"(O[k].z), "f"(O[k].w)
                     : "memory");
    }
}

extern "C" void kernel_launch(void* const* d_in, const int* in_sizes, int n_in,
                              void* d_out, int out_size)
{
    const float* a       = (const float*)d_in[0];
    const float* b       = (const float*)d_in[1];
    const int*   idx_a   = (const int*)d_in[2];
    const int*   idx_out = (const int*)d_in[3];
    float*       out     = (float*)d_out;

    const int E = in_sizes[1] / B_ROW;

    // Output buffer is poisoned by the harness; zero it (memset node is graph-capturable).
    cudaMemsetAsync(d_out, 0, (size_t)out_size * sizeof(float));

    const int threads = 128;
    const long long total = (long long)E * 8;
    const int blocks = (int)((total + threads - 1) / threads);
    spp_kernel<<<blocks, threads>>>(a, b, idx_a, idx_out, out, E);
}

// round 15
// speedup vs baseline: 1.0183x; 1.0183x over previous
#include <cuda_runtime.h>
#include <cstddef>

// SegmentedPolynomialProductJit: out[e,k,u] = sum_{paths (i,j,k,c)} c * a[idx_a[e], i, u] * b[e, j, u]
// scatter-added into out[idx_out[e]].
// SA=4, SB=3, SC=4, U=32, paths: all (i,j), k=(i+j)%4, c=0.1*(i+1)+0.01*(j+1).
//
// Evidence log:
// R4:  baseline 150.9us, 1.0 GB HBM vs ~590 MB floor -> b-stream L2 thrash.
// R8:  __ldcs on b -> 129.0us, 775 MB. WIN.
// R12: a pinned via v8 evict_last -> traffic UNCHANGED. a-miss hypothesis dead.
// R13: 128-thr blocks -> 126.0us, occ 53.5%, DRAM 77.6%. Champion.
// R14: forced 40 regs -> occ 63.8% but DRAM fell, 129.8us. Occupancy model dead;
//      >53% occ doesn't help. Limiter = traffic (~185 MB over floor).
// R15: pin OUT lines (last untested excess source: 32M scattered RMW atomics over
//      51 MB) via createpolicy evict_last + red.global.L2::cache_hint (no width
//      restriction, unlike bare evict_* ld forms).

#define SA 4
#define SB 3
#define SC 4
#define UE 32
#define A_ROW (SA * UE)   // 128 floats
#define B_ROW (SB * UE)   // 96 floats
#define O_ROW (SC * UE)   // 128 floats

// 8 threads per edge; each thread owns one float4 (4 consecutive u) across all segments.
__global__ __launch_bounds__(128) void spp_kernel(
    const float* __restrict__ a,
    const float* __restrict__ b,
    const int*   __restrict__ idx_a,
    const int*   __restrict__ idx_out,
    float*       __restrict__ out,
    int E)
{
    long long tid = (long long)blockIdx.x * blockDim.x + threadIdx.x;
    int e = (int)(tid >> 3);
    if (e >= E) return;
    int q = (int)(tid & 7);          // float4 index within a U=32 segment (8 quads)

    const int ia = __ldg(idx_a + e);
    const int io = __ldg(idx_out + e);

    const float4* arow = reinterpret_cast<const float4*>(a) + (size_t)ia * (A_ROW / 4) + q;
    const float4* brow = reinterpret_cast<const float4*>(b) + (size_t)e  * (B_ROW / 4) + q;

    float4 A[SA], B[SB];
#pragma unroll
    for (int i = 0; i < SA; i++) A[i] = __ldg(arow + i * (UE / 4));      // reused: keep cached
#pragma unroll
    for (int j = 0; j < SB; j++) B[j] = __ldcs(brow + j * (UE / 4));     // read-once: streaming

    float4 O[SC];
#pragma unroll
    for (int k = 0; k < SC; k++) { O[k].x = 0.f; O[k].y = 0.f; O[k].z = 0.f; O[k].w = 0.f; }

#pragma unroll
    for (int i = 0; i < SA; i++) {
#pragma unroll
        for (int j = 0; j < SB; j++) {
            const int k = (i + j) & 3;
            const float c = 0.1f * (float)(i + 1) + 0.01f * (float)(j + 1);
            // pre-scale a by the path coefficient, then one fma per component
            float cax = c * A[i].x;
            float cay = c * A[i].y;
            float caz = c * A[i].z;
            float caw = c * A[i].w;
            O[k].x = fmaf(cax, B[j].x, O[k].x);
            O[k].y = fmaf(cay, B[j].y, O[k].y);
            O[k].z = fmaf(caz, B[j].z, O[k].z);
            O[k].w = fmaf(caw, B[j].w, O[k].w);
        }
    }

    // Keep the randomly-revisited out lines resident in L2 across the kernel.
    unsigned long long pol;
    asm("createpolicy.fractional.L2::evict_last.b64 %0, 1.0;" : "=l"(pol));

    float* orow = out + (size_t)io * O_ROW + q * 4;
#pragma unroll
    for (int k = 0; k < SC; k++) {
        float* p = orow + k * UE;
        asm volatile("red.global.L2::cache_hint.add.v4.f32 [%0], {%1, %2, %3, %4}, %5;"
                     :: "l"(p), "f"(O[k].x), "f"(O[k].y), "f"(O[k].z), "f"(O[k].w),
                        "l"(pol)
                     : "memory");
    }
}

extern "C" void kernel_launch(void* const* d_in, const int* in_sizes, int n_in,
                              void* d_out, int out_size)
{
    const float* a       = (const float*)d_in[0];
    const float* b       = (const float*)d_in[1];
    const int*   idx_a   = (const int*)d_in[2];
    const int*   idx_out = (const int*)d_in[3];
    float*       out     = (float*)d_out;

    const int E = in_sizes[1] / B_ROW;

    // Output buffer is poisoned by the harness; zero it (memset node is graph-capturable).
    cudaMemsetAsync(d_out, 0, (size_t)out_size * sizeof(float));

    const int threads = 128;
    const long long total = (long long)E * 8;
    const int blocks = (int)((total + threads - 1) / threads);
    spp_kernel<<<blocks, threads>>>(a, b, idx_a, idx_out, out, E);
}